// round 7
// baseline (speedup 1.0000x reference)
#include <cuda_runtime.h>
#include <cuda_bf16.h>
#include <math.h>
#include <stdint.h>

#define BB 4
#define TT 2048
#define CC 1024
#define HH 16
#define DD 64
#define MM (BB*TT)
#define MH 4096                   // rows done by HMMA path
// rows [MH, MM) done by FFMA path

// ---------------- scratch (device globals; no runtime alloc) ----------------
__device__ float g_q[(size_t)BB*HH*TT*DD];
__device__ float g_k[(size_t)BB*HH*TT*DD];
__device__ float g_v[(size_t)BB*HH*TT*DD];
__device__ __nv_bfloat16 g_xh[(size_t)MM*CC], g_xl[(size_t)MM*CC];
__device__ __nv_bfloat16 g_ah[(size_t)MM*CC], g_al[(size_t)MM*CC];
__device__ __nv_bfloat16 g_wh[4][(size_t)CC*CC], g_wl[4][(size_t)CC*CC];

// ---------------- base-ISA tensor helpers (compute_103-safe) ----------------
__device__ __forceinline__ uint32_t smem_u32(const void* p) {
    uint32_t a;
    asm("{ .reg .u64 t; cvta.to.shared.u64 t, %1; cvt.u32.u64 %0, t; }"
        : "=r"(a) : "l"(p));
    return a;
}
__device__ __forceinline__ void cp16(uint32_t dst, const void* src) {
    asm volatile("cp.async.cg.shared.global [%0], [%1], 16;" :: "r"(dst), "l"(src));
}
__device__ __forceinline__ void cp_commit() { asm volatile("cp.async.commit_group;"); }
template<int N> __device__ __forceinline__ void cp_wait() {
    asm volatile("cp.async.wait_group %0;" :: "n"(N));
}
__device__ __forceinline__ void ldsm4(uint32_t* r, uint32_t addr) {
    asm volatile("ldmatrix.sync.aligned.m8n8.x4.shared.b16 {%0,%1,%2,%3}, [%4];"
                 : "=r"(r[0]), "=r"(r[1]), "=r"(r[2]), "=r"(r[3]) : "r"(addr));
}
__device__ __forceinline__ void mma16816(float* d, const uint32_t* a, const uint32_t* b) {
    asm volatile(
        "mma.sync.aligned.m16n8k16.row.col.f32.bf16.bf16.f32 "
        "{%0,%1,%2,%3}, {%4,%5,%6,%7}, {%8,%9}, {%0,%1,%2,%3};"
        : "+f"(d[0]), "+f"(d[1]), "+f"(d[2]), "+f"(d[3])
        : "r"(a[0]), "r"(a[1]), "r"(a[2]), "r"(a[3]), "r"(b[0]), "r"(b[1]));
}
// reconstruct 4 fp32 from bf16 hi/lo pairs
__device__ __forceinline__ float4 rebuild4(const __nv_bfloat16* hi, const __nv_bfloat16* lo) {
    const __nv_bfloat162* h = (const __nv_bfloat162*)hi;
    const __nv_bfloat162* l = (const __nv_bfloat162*)lo;
    float2 a = __bfloat1622float2(h[0]), b = __bfloat1622float2(h[1]);
    float2 c = __bfloat1622float2(l[0]), d = __bfloat1622float2(l[1]);
    return make_float4(a.x + c.x, a.y + c.y, b.x + d.x, b.y + d.y);
}

// ---------------------------------------------------------------------------
// fp32 -> (bf16 hi, bf16 lo) split kernels
// ---------------------------------------------------------------------------
__device__ __forceinline__ void split_body(const float* __restrict__ src,
                                           __nv_bfloat16* __restrict__ hi,
                                           __nv_bfloat16* __restrict__ lo, int i) {
    float4 v = ((const float4*)src)[i];
    __nv_bfloat16 h0 = __float2bfloat16(v.x), h1 = __float2bfloat16(v.y);
    __nv_bfloat16 h2 = __float2bfloat16(v.z), h3 = __float2bfloat16(v.w);
    __nv_bfloat16 l0 = __float2bfloat16(v.x - __bfloat162float(h0));
    __nv_bfloat16 l1 = __float2bfloat16(v.y - __bfloat162float(h1));
    __nv_bfloat16 l2 = __float2bfloat16(v.z - __bfloat162float(h2));
    __nv_bfloat16 l3 = __float2bfloat16(v.w - __bfloat162float(h3));
    ((__nv_bfloat162*)hi)[2 * i]     = __nv_bfloat162(h0, h1);
    ((__nv_bfloat162*)hi)[2 * i + 1] = __nv_bfloat162(h2, h3);
    ((__nv_bfloat162*)lo)[2 * i]     = __nv_bfloat162(l0, l1);
    ((__nv_bfloat162*)lo)[2 * i + 1] = __nv_bfloat162(l2, l3);
}
__global__ __launch_bounds__(256) void split_bf16(const float* __restrict__ src,
                                                  __nv_bfloat16* __restrict__ hi,
                                                  __nv_bfloat16* __restrict__ lo, int n4) {
    int i = blockIdx.x * 256 + threadIdx.x;
    if (i < n4) split_body(src, hi, lo, i);
}
__global__ __launch_bounds__(256) void split_w4(const float* __restrict__ w0,
                                                const float* __restrict__ w1,
                                                const float* __restrict__ w2,
                                                const float* __restrict__ w3,
                                                __nv_bfloat16* __restrict__ hi,
                                                __nv_bfloat16* __restrict__ lo) {
    const int which = blockIdx.y;
    const float* src = which == 0 ? w0 : which == 1 ? w1 : which == 2 ? w2 : w3;
    hi += (size_t)which * CC * CC;
    lo += (size_t)which * CC * CC;
    int i = blockIdx.x * 256 + threadIdx.x;
    if (i < CC * CC / 4) split_body(src, hi, lo, i);
}

// ---------------------------------------------------------------------------
// Hybrid GEMM: out[m][n] = sum_k A[m][k]*B[n][k]
//  - HMMA CTAs (3-pass split bf16): rows [0, MH), 128x128 tiles
//  - FFMA CTAs (fp32, reconstructed from hi+lo): rows [MH, 8192), 128x128 tiles
// Both CTA types identical footprint -> 2 CTAs/SM; bid pattern pairs one of
// each per SM so tensor + fma pipes run concurrently.
// ---------------------------------------------------------------------------
#define ROWB 80
#define MATB (128 * ROWB)
#define STAGEB (4 * MATB)          // 40960
#define NCHUNK (CC / 32)           // 32
#define TH 256                     // (MH/128) * 8
#define HYB_GRID 512

template<int REMAP>
__global__ __launch_bounds__(256, 2)
void hyb_gemm(const __nv_bfloat16* __restrict__ Ah_g, const __nv_bfloat16* __restrict__ Al_g,
              const __nv_bfloat16* __restrict__ Bh_g, const __nv_bfloat16* __restrict__ Bl_g,
              float* __restrict__ out) {
    extern __shared__ __align__(128) char smem[];          // HMMA stages (2*STAGEB)
    __shared__ float sA[16][132], sB[16][132];              // FFMA stages

    const int tid = threadIdx.x;
    const int bid = blockIdx.x;
    const int w = bid / 148;                 // wave-row
    const int i = bid - w * 148;
    const bool isH = (((i + w) & 1) == 0);
    const int idx = 74 * w + (i >> 1);       // index within type

    if (isH) {
        // =================== HMMA path (rows [0, MH)) ===================
        const int wid = tid >> 5, lane = tid & 31;
        const int m0 = (idx >> 3) * 128;
        const int n0 = (idx & 7) * 128;
        const uint32_t sbase = smem_u32(smem);

        const char* srcs[4] = {
            (const char*)(Ah_g + (size_t)m0 * CC), (const char*)(Al_g + (size_t)m0 * CC),
            (const char*)(Bh_g + (size_t)n0 * CC), (const char*)(Bl_g + (size_t)n0 * CC)};

        auto stage_load = [&](int kc, int st) {
            const uint32_t dst0 = sbase + st * STAGEB;
            const size_t koff = (size_t)kc * 64;
#pragma unroll
            for (int mtx = 0; mtx < 4; mtx++) {
#pragma unroll
                for (int h2 = 0; h2 < 2; h2++) {
                    const int id2 = h2 * 256 + tid;
                    const int r = id2 >> 2, c = id2 & 3;
                    cp16(dst0 + mtx * MATB + r * ROWB + c * 16,
                         srcs[mtx] + (size_t)r * 2048 + koff + c * 16);
                }
            }
        };

        const int wm = wid >> 2, wn = wid & 3;
        const int g = lane >> 2, tig = lane & 3;
        float acc[4][4][4] = {};

        const int a_row = wm * 64 + (lane & 15);
        const int a_col = (lane >> 4) * 16;
        const int b_row = wn * 32 + (lane & 7) + ((lane >> 4) & 1) * 8;
        const int b_col = ((lane >> 3) & 1) * 16;

        stage_load(0, 0);
        cp_commit();

        for (int c = 0; c < NCHUNK; c++) {
            const int st = c & 1;
            if (c + 1 < NCHUNK) { stage_load(c + 1, (c + 1) & 1); cp_commit(); cp_wait<1>(); }
            else                { cp_wait<0>(); }
            __syncthreads();

            const uint32_t sAh = sbase + st * STAGEB;
            const uint32_t sAl = sAh + MATB;
            const uint32_t sBh = sAh + 2 * MATB;
            const uint32_t sBl = sAh + 3 * MATB;

#pragma unroll
            for (int s = 0; s < 2; s++) {
                const int k16 = s * 32;
                uint32_t bfh[2][4], bfl[2][4];
#pragma unroll
                for (int np = 0; np < 2; np++) {
                    const uint32_t bo = (b_row + np * 16) * ROWB + b_col + k16;
                    ldsm4(bfh[np], sBh + bo);
                    ldsm4(bfl[np], sBl + bo);
                }
#pragma unroll
                for (int mt = 0; mt < 4; mt++) {
                    uint32_t afh[4], afl[4];
                    const uint32_t ao = (a_row + mt * 16) * ROWB + a_col + k16;
                    ldsm4(afh, sAh + ao);
                    ldsm4(afl, sAl + ao);
#pragma unroll
                    for (int nt = 0; nt < 4; nt++) {
                        const int np = nt >> 1, hf = (nt & 1) * 2;
                        mma16816(acc[mt][nt], afh, &bfh[np][hf]);
                        mma16816(acc[mt][nt], afh, &bfl[np][hf]);
                        mma16816(acc[mt][nt], afl, &bfh[np][hf]);
                    }
                }
            }
            __syncthreads();
        }

#pragma unroll
        for (int mt = 0; mt < 4; mt++) {
#pragma unroll
            for (int half = 0; half < 2; half++) {
                const int m = m0 + wm * 64 + mt * 16 + g + half * 8;
                float* dst;
                if (REMAP) {
                    const int b = m >> 11, t = m & 2047;
                    dst = out + (((size_t)b * HH) * TT + t) * DD;
                } else {
                    dst = out + (size_t)m * CC;
                }
#pragma unroll
                for (int nt = 0; nt < 4; nt++) {
                    const int n = n0 + wn * 32 + nt * 8 + tig * 2;
                    float2 v = make_float2(acc[mt][nt][half * 2], acc[mt][nt][half * 2 + 1]);
                    if (REMAP) {
                        const int h2 = n >> 6, d = n & 63;
                        *(float2*)(dst + (size_t)h2 * TT * DD + d) = v;
                    } else {
                        *(float2*)(dst + n) = v;
                    }
                }
            }
        }
    } else {
        // =================== FFMA path (rows [MH, 8192)) ===================
        const int m0 = MH + (idx >> 3) * 128;
        const int n0 = (idx & 7) * 128;
        const int lm = tid >> 1;               // 0..127
        const int lk8 = (tid & 1) * 8;         // 0 or 8
        const int tx = tid & 15, ty = tid >> 4;

        const __nv_bfloat16* aH = Ah_g + (size_t)(m0 + lm) * CC + lk8;
        const __nv_bfloat16* aL = Al_g + (size_t)(m0 + lm) * CC + lk8;
        const __nv_bfloat16* bH = Bh_g + (size_t)(n0 + lm) * CC + lk8;
        const __nv_bfloat16* bL = Bl_g + (size_t)(n0 + lm) * CC + lk8;

        float acc[8][8] = {};

        for (int kb = 0; kb < CC; kb += 16) {
            float4 a0 = rebuild4(aH + kb, aL + kb);
            float4 a1 = rebuild4(aH + kb + 4, aL + kb + 4);
            float4 b0 = rebuild4(bH + kb, bL + kb);
            float4 b1 = rebuild4(bH + kb + 4, bL + kb + 4);
            __syncthreads();
            sA[lk8 + 0][lm] = a0.x; sA[lk8 + 1][lm] = a0.y;
            sA[lk8 + 2][lm] = a0.z; sA[lk8 + 3][lm] = a0.w;
            sA[lk8 + 4][lm] = a1.x; sA[lk8 + 5][lm] = a1.y;
            sA[lk8 + 6][lm] = a1.z; sA[lk8 + 7][lm] = a1.w;
            sB[lk8 + 0][lm] = b0.x; sB[lk8 + 1][lm] = b0.y;
            sB[lk8 + 2][lm] = b0.z; sB[lk8 + 3][lm] = b0.w;
            sB[lk8 + 4][lm] = b1.x; sB[lk8 + 5][lm] = b1.y;
            sB[lk8 + 6][lm] = b1.z; sB[lk8 + 7][lm] = b1.w;
            __syncthreads();
#pragma unroll
            for (int kk = 0; kk < 16; kk++) {
                float av[8], bv[8];
                *(float4*)&av[0] = *(const float4*)&sA[kk][ty * 8];
                *(float4*)&av[4] = *(const float4*)&sA[kk][ty * 8 + 4];
                *(float4*)&bv[0] = *(const float4*)&sB[kk][tx * 8];
                *(float4*)&bv[4] = *(const float4*)&sB[kk][tx * 8 + 4];
#pragma unroll
                for (int ii = 0; ii < 8; ii++)
#pragma unroll
                    for (int jj = 0; jj < 8; jj++) acc[ii][jj] += av[ii] * bv[jj];
            }
        }

#pragma unroll
        for (int ii = 0; ii < 8; ii++) {
            const int m = m0 + ty * 8 + ii;
            float* dst;
            if (REMAP) {
                const int b = m >> 11, t = m & 2047;
                dst = out + (((size_t)b * HH) * TT + t) * DD;
            } else {
                dst = out + (size_t)m * CC;
            }
            const int n = n0 + tx * 8;
            if (REMAP) {
                const int h2 = n >> 6, d = n & 63;
                *(float4*)(dst + (size_t)h2 * TT * DD + d)     = *(float4*)&acc[ii][0];
                *(float4*)(dst + (size_t)h2 * TT * DD + d + 4) = *(float4*)&acc[ii][4];
            } else {
                *(float4*)(dst + n)     = *(float4*)&acc[ii][0];
                *(float4*)(dst + n + 4) = *(float4*)&acc[ii][4];
            }
        }
    }
}

// ---------------------------------------------------------------------------
// Flash attention (fp32, causal) — unchanged from R6 (known good).
// ---------------------------------------------------------------------------
#define FS 68

__global__ __launch_bounds__(256) void flash_kernel() {
    extern __shared__ float sm[];
    float* Qs = sm;
    float* Ks = Qs + 64 * 64;
    float* Vs = Ks + 64 * FS;
    float* Ps = Vs + 64 * FS;

    const int tid = threadIdx.x;
    const int tx = tid & 15;
    const int ty = tid >> 4;
    const int q0 = (gridDim.x - 1 - blockIdx.x) * 64;
    const int bh = blockIdx.y;
    const int b = bh / HH, h = bh % HH;

    const float* Qg = g_q + (size_t)bh * TT * DD;
    const float* Kg = g_k + (size_t)bh * TT * DD;
    const float* Vg = g_v + (size_t)bh * TT * DD;

    for (int i = tid; i < 1024; i += 256) {
        const int r = i >> 4, dv = (i & 15) << 2;
        *(float4*)&Qs[r * 64 + dv] = *(const float4*)(Qg + (size_t)(q0 + r) * DD + dv);
    }

    float m_i[4], l_i[4], acc[4][4] = {};
#pragma unroll
    for (int i = 0; i < 4; i++) { m_i[i] = -INFINITY; l_i[i] = 0.f; }

    const int ktiles = (q0 >> 6) + 1;
    const unsigned FULL = 0xffffffffu;

    for (int kt = 0; kt < ktiles; kt++) {
        const int k0 = kt << 6;
        __syncthreads();
        for (int i = tid; i < 1024; i += 256) {
            const int r = i >> 4, dv = (i & 15) << 2;
            *(float4*)&Ks[r * FS + dv] = *(const float4*)(Kg + (size_t)(k0 + r) * DD + dv);
            *(float4*)&Vs[r * FS + dv] = *(const float4*)(Vg + (size_t)(k0 + r) * DD + dv);
        }
        __syncthreads();

        float s[4][4] = {};
#pragma unroll 4
        for (int d4 = 0; d4 < 16; d4++) {
            float4 qv[4], kv[4];
#pragma unroll
            for (int i = 0; i < 4; i++) qv[i] = *(const float4*)&Qs[((ty << 2) + i) * 64 + (d4 << 2)];
#pragma unroll
            for (int j = 0; j < 4; j++) kv[j] = *(const float4*)&Ks[((tx << 2) + j) * FS + (d4 << 2)];
#pragma unroll
            for (int i = 0; i < 4; i++)
#pragma unroll
                for (int j = 0; j < 4; j++)
                    s[i][j] += qv[i].x * kv[j].x + qv[i].y * kv[j].y +
                               qv[i].z * kv[j].z + qv[i].w * kv[j].w;
        }

        const bool diag = (kt == ktiles - 1);
#pragma unroll
        for (int i = 0; i < 4; i++) {
            const int qg = q0 + (ty << 2) + i;
#pragma unroll
            for (int j = 0; j < 4; j++) {
                s[i][j] *= 0.125f;
                if (diag && (k0 + (tx << 2) + j > qg)) s[i][j] = -INFINITY;
            }
        }

#pragma unroll
        for (int i = 0; i < 4; i++) {
            float mx = fmaxf(fmaxf(s[i][0], s[i][1]), fmaxf(s[i][2], s[i][3]));
#pragma unroll
            for (int off = 8; off; off >>= 1)
                mx = fmaxf(mx, __shfl_xor_sync(FULL, mx, off, 16));
            const float m_new = fmaxf(m_i[i], mx);
            const float corr = __expf(m_i[i] - m_new);
            float4 p4;
            p4.x = __expf(s[i][0] - m_new); p4.y = __expf(s[i][1] - m_new);
            p4.z = __expf(s[i][2] - m_new); p4.w = __expf(s[i][3] - m_new);
            *(float4*)&Ps[((ty << 2) + i) * FS + (tx << 2)] = p4;
            float rs = p4.x + p4.y + p4.z + p4.w;
#pragma unroll
            for (int off = 8; off; off >>= 1)
                rs += __shfl_xor_sync(FULL, rs, off, 16);
            l_i[i] = l_i[i] * corr + rs;
            m_i[i] = m_new;
#pragma unroll
            for (int j = 0; j < 4; j++) acc[i][j] *= corr;
        }
        __syncthreads();

#pragma unroll 4
        for (int k4 = 0; k4 < 16; k4++) {
            float4 vv[4], pr[4];
#pragma unroll
            for (int kq = 0; kq < 4; kq++) vv[kq] = *(const float4*)&Vs[((k4 << 2) + kq) * FS + (tx << 2)];
#pragma unroll
            for (int i = 0; i < 4; i++) pr[i] = *(const float4*)&Ps[((ty << 2) + i) * FS + (k4 << 2)];
#pragma unroll
            for (int i = 0; i < 4; i++) {
                acc[i][0] += pr[i].x * vv[0].x + pr[i].y * vv[1].x + pr[i].z * vv[2].x + pr[i].w * vv[3].x;
                acc[i][1] += pr[i].x * vv[0].y + pr[i].y * vv[1].y + pr[i].z * vv[2].y + pr[i].w * vv[3].y;
                acc[i][2] += pr[i].x * vv[0].z + pr[i].y * vv[1].z + pr[i].z * vv[2].z + pr[i].w * vv[3].z;
                acc[i][3] += pr[i].x * vv[0].w + pr[i].y * vv[1].w + pr[i].z * vv[2].w + pr[i].w * vv[3].w;
            }
        }
    }

#pragma unroll
    for (int i = 0; i < 4; i++) {
        const float inv = 1.0f / l_i[i];
        const int q = q0 + (ty << 2) + i;
        const size_t base = (size_t)(b * TT + q) * CC + h * DD + (tx << 2);
        __nv_bfloat16 hh[4], ll[4];
#pragma unroll
        for (int j = 0; j < 4; j++) {
            const float v = acc[i][j] * inv;
            hh[j] = __float2bfloat16(v);
            ll[j] = __float2bfloat16(v - __bfloat162float(hh[j]));
        }
        *(__nv_bfloat162*)(g_ah + base)     = __nv_bfloat162(hh[0], hh[1]);
        *(__nv_bfloat162*)(g_ah + base + 2) = __nv_bfloat162(hh[2], hh[3]);
        *(__nv_bfloat162*)(g_al + base)     = __nv_bfloat162(ll[0], ll[1]);
        *(__nv_bfloat162*)(g_al + base + 2) = __nv_bfloat162(ll[2], ll[3]);
    }
}

// ---------------------------------------------------------------------------
extern "C" void kernel_launch(void* const* d_in, const int* in_sizes, int n_in,
                              void* d_out, int out_size) {
    const float* x  = (const float*)d_in[0];
    const float* Wq = (const float*)d_in[1];
    const float* Wk = (const float*)d_in[2];
    const float* Wv = (const float*)d_in[3];
    const float* Wo = (const float*)d_in[4];
    float* out = (float*)d_out;

    float *q, *k, *v;
    cudaGetSymbolAddress((void**)&q, g_q);
    cudaGetSymbolAddress((void**)&k, g_k);
    cudaGetSymbolAddress((void**)&v, g_v);
    __nv_bfloat16 *xh, *xl, *ah, *al, *wh, *wl;
    cudaGetSymbolAddress((void**)&xh, g_xh);
    cudaGetSymbolAddress((void**)&xl, g_xl);
    cudaGetSymbolAddress((void**)&ah, g_ah);
    cudaGetSymbolAddress((void**)&al, g_al);
    cudaGetSymbolAddress((void**)&wh, g_wh);
    cudaGetSymbolAddress((void**)&wl, g_wl);

    split_bf16<<<(MM * CC / 4 + 255) / 256, 256>>>(x, xh, xl, MM * CC / 4);
    split_w4<<<dim3((CC * CC / 4 + 255) / 256, 4), 256>>>(Wq, Wk, Wv, Wo, wh, wl);

    const int gemm_smem = 2 * STAGEB;  // 81920
    cudaFuncSetAttribute(hyb_gemm<1>, cudaFuncAttributeMaxDynamicSharedMemorySize, gemm_smem);
    cudaFuncSetAttribute(hyb_gemm<0>, cudaFuncAttributeMaxDynamicSharedMemorySize, gemm_smem);

    hyb_gemm<1><<<HYB_GRID, 256, gemm_smem>>>(xh, xl, wh + 0 * (size_t)CC * CC, wl + 0 * (size_t)CC * CC, q);
    hyb_gemm<1><<<HYB_GRID, 256, gemm_smem>>>(xh, xl, wh + 1 * (size_t)CC * CC, wl + 1 * (size_t)CC * CC, k);
    hyb_gemm<1><<<HYB_GRID, 256, gemm_smem>>>(xh, xl, wh + 2 * (size_t)CC * CC, wl + 2 * (size_t)CC * CC, v);

    const size_t shmem = (size_t)(64 * 64 + 3 * 64 * FS) * sizeof(float);
    cudaFuncSetAttribute(flash_kernel, cudaFuncAttributeMaxDynamicSharedMemorySize, (int)shmem);
    flash_kernel<<<dim3(TT / 64, BB * HH), 256, shmem>>>();

    hyb_gemm<0><<<HYB_GRID, 256, gemm_smem>>>(ah, al, wh + 3 * (size_t)CC * CC, wl + 3 * (size_t)CC * CC, out);
}

// round 10
// speedup vs baseline: 3.2486x; 3.2486x over previous
#include <cuda_runtime.h>
#include <cuda_bf16.h>
#include <math.h>
#include <stdint.h>

#define BB 4
#define TT 2048
#define CC 1024
#define HH 16
#define DD 64
#define MM (BB*TT)

// ---------------- scratch (device globals; no runtime alloc) ----------------
__device__ __nv_bfloat16 g_qh[(size_t)BB*HH*TT*DD], g_ql[(size_t)BB*HH*TT*DD];
__device__ __nv_bfloat16 g_kh[(size_t)BB*HH*TT*DD], g_kl[(size_t)BB*HH*TT*DD];
__device__ __nv_bfloat16 g_vh[(size_t)BB*HH*TT*DD], g_vl[(size_t)BB*HH*TT*DD];
__device__ __nv_bfloat16 g_xh[(size_t)MM*CC], g_xl[(size_t)MM*CC];
__device__ __nv_bfloat16 g_ah[(size_t)MM*CC], g_al[(size_t)MM*CC];
__device__ __nv_bfloat16 g_wh[4][(size_t)CC*CC], g_wl[4][(size_t)CC*CC];

// ---------------- base-ISA tensor helpers (compute_103-safe) ----------------
__device__ __forceinline__ uint32_t smem_u32(const void* p) {
    uint32_t a;
    asm("{ .reg .u64 t; cvta.to.shared.u64 t, %1; cvt.u32.u64 %0, t; }"
        : "=r"(a) : "l"(p));
    return a;
}
__device__ __forceinline__ void cp16(uint32_t dst, const void* src) {
    asm volatile("cp.async.cg.shared.global [%0], [%1], 16;" :: "r"(dst), "l"(src));
}
__device__ __forceinline__ void cp_commit() { asm volatile("cp.async.commit_group;"); }
template<int N> __device__ __forceinline__ void cp_wait() {
    asm volatile("cp.async.wait_group %0;" :: "n"(N));
}
__device__ __forceinline__ void ldsm4(uint32_t* r, uint32_t addr) {
    asm volatile("ldmatrix.sync.aligned.m8n8.x4.shared.b16 {%0,%1,%2,%3}, [%4];"
                 : "=r"(r[0]), "=r"(r[1]), "=r"(r[2]), "=r"(r[3]) : "r"(addr));
}
__device__ __forceinline__ void ldsm4t(uint32_t* r, uint32_t addr) {
    asm volatile("ldmatrix.sync.aligned.m8n8.x4.trans.shared.b16 {%0,%1,%2,%3}, [%4];"
                 : "=r"(r[0]), "=r"(r[1]), "=r"(r[2]), "=r"(r[3]) : "r"(addr));
}
__device__ __forceinline__ void mma16816(float* d, const uint32_t* a, const uint32_t* b) {
    asm volatile(
        "mma.sync.aligned.m16n8k16.row.col.f32.bf16.bf16.f32 "
        "{%0,%1,%2,%3}, {%4,%5,%6,%7}, {%8,%9}, {%0,%1,%2,%3};"
        : "+f"(d[0]), "+f"(d[1]), "+f"(d[2]), "+f"(d[3])
        : "r"(a[0]), "r"(a[1]), "r"(a[2]), "r"(a[3]), "r"(b[0]), "r"(b[1]));
}
// split 2 fp32 into packed bf16x2 (hi) + packed bf16x2 (lo residual)
__device__ __forceinline__ void splitpack(float a, float b, uint32_t& h, uint32_t& l) {
    __nv_bfloat162 hh = __floats2bfloat162_rn(a, b);
    float2 hf = __bfloat1622float2(hh);
    __nv_bfloat162 ll = __floats2bfloat162_rn(a - hf.x, b - hf.y);
    h = *reinterpret_cast<uint32_t*>(&hh);
    l = *reinterpret_cast<uint32_t*>(&ll);
}

// ---------------------------------------------------------------------------
// fp32 -> (bf16 hi, bf16 lo) split kernels (inputs x, W only)
// ---------------------------------------------------------------------------
__device__ __forceinline__ void split_body(const float* __restrict__ src,
                                           __nv_bfloat16* __restrict__ hi,
                                           __nv_bfloat16* __restrict__ lo, int i) {
    float4 v = ((const float4*)src)[i];
    uint32_t h0, l0, h1, l1;
    splitpack(v.x, v.y, h0, l0);
    splitpack(v.z, v.w, h1, l1);
    ((uint32_t*)hi)[2 * i] = h0; ((uint32_t*)hi)[2 * i + 1] = h1;
    ((uint32_t*)lo)[2 * i] = l0; ((uint32_t*)lo)[2 * i + 1] = l1;
}
__global__ __launch_bounds__(256) void split_bf16(const float* __restrict__ src,
                                                  __nv_bfloat16* __restrict__ hi,
                                                  __nv_bfloat16* __restrict__ lo, int n4) {
    int i = blockIdx.x * 256 + threadIdx.x;
    if (i < n4) split_body(src, hi, lo, i);
}
__global__ __launch_bounds__(256) void split_w4(const float* __restrict__ w0,
                                                const float* __restrict__ w1,
                                                const float* __restrict__ w2,
                                                const float* __restrict__ w3,
                                                __nv_bfloat16* __restrict__ hi,
                                                __nv_bfloat16* __restrict__ lo) {
    const int which = blockIdx.y;
    const float* src = which == 0 ? w0 : which == 1 ? w1 : which == 2 ? w2 : w3;
    hi += (size_t)which * CC * CC;
    lo += (size_t)which * CC * CC;
    int i = blockIdx.x * 256 + threadIdx.x;
    if (i < CC * CC / 4) split_body(src, hi, lo, i);
}

// ---------------------------------------------------------------------------
// HMMA split-bf16 GEMM (R6 structure). REMAP=1 -> bf16 hi/lo to [B,H,T,D];
// REMAP=0 -> fp32 row-major [M,1024].
// ---------------------------------------------------------------------------
#define ROWB 80
#define MATB (128 * ROWB)
#define STAGEB (4 * MATB)
#define NCHUNK (CC / 32)

template<int REMAP>
__global__ __launch_bounds__(256)
void mma_gemm(const __nv_bfloat16* __restrict__ Ah_g, const __nv_bfloat16* __restrict__ Al_g,
              const __nv_bfloat16* __restrict__ Bh_g, const __nv_bfloat16* __restrict__ Bl_g,
              float* __restrict__ outF,
              __nv_bfloat16* __restrict__ outH, __nv_bfloat16* __restrict__ outL) {
    extern __shared__ __align__(128) char smem[];

    const int tid = threadIdx.x;
    const int wid = tid >> 5;
    const int lane = tid & 31;
    const int m0 = blockIdx.y * 128;
    const int n0 = blockIdx.x * 128;
    const uint32_t sbase = smem_u32(smem);

    const char* srcs[4] = {
        (const char*)(Ah_g + (size_t)m0 * CC), (const char*)(Al_g + (size_t)m0 * CC),
        (const char*)(Bh_g + (size_t)n0 * CC), (const char*)(Bl_g + (size_t)n0 * CC)};

    auto stage_load = [&](int kc, int st) {
        const uint32_t dst0 = sbase + st * STAGEB;
        const size_t koff = (size_t)kc * 64;
#pragma unroll
        for (int mtx = 0; mtx < 4; mtx++) {
#pragma unroll
            for (int h2 = 0; h2 < 2; h2++) {
                const int idx = h2 * 256 + tid;
                const int r = idx >> 2, c = idx & 3;
                cp16(dst0 + mtx * MATB + r * ROWB + c * 16,
                     srcs[mtx] + (size_t)r * 2048 + koff + c * 16);
            }
        }
    };

    const int wm = wid >> 2, wn = wid & 3;
    const int g = lane >> 2, tig = lane & 3;
    float acc[4][4][4] = {};

    const int a_row = wm * 64 + (lane & 15);
    const int a_col = (lane >> 4) * 16;
    const int b_row = wn * 32 + (lane & 7) + ((lane >> 4) & 1) * 8;
    const int b_col = ((lane >> 3) & 1) * 16;

    stage_load(0, 0);
    cp_commit();

    for (int c = 0; c < NCHUNK; c++) {
        const int st = c & 1;
        if (c + 1 < NCHUNK) { stage_load(c + 1, (c + 1) & 1); cp_commit(); cp_wait<1>(); }
        else                { cp_wait<0>(); }
        __syncthreads();

        const uint32_t sAh = sbase + st * STAGEB;
        const uint32_t sAl = sAh + MATB;
        const uint32_t sBh = sAh + 2 * MATB;
        const uint32_t sBl = sAh + 3 * MATB;

#pragma unroll
        for (int s = 0; s < 2; s++) {
            const int k16 = s * 32;
            uint32_t bfh[2][4], bfl[2][4];
#pragma unroll
            for (int np = 0; np < 2; np++) {
                const uint32_t bo = (b_row + np * 16) * ROWB + b_col + k16;
                ldsm4(bfh[np], sBh + bo);
                ldsm4(bfl[np], sBl + bo);
            }
#pragma unroll
            for (int mt = 0; mt < 4; mt++) {
                uint32_t afh[4], afl[4];
                const uint32_t ao = (a_row + mt * 16) * ROWB + a_col + k16;
                ldsm4(afh, sAh + ao);
                ldsm4(afl, sAl + ao);
#pragma unroll
                for (int nt = 0; nt < 4; nt++) {
                    const int np = nt >> 1, hf = (nt & 1) * 2;
                    mma16816(acc[mt][nt], afh, &bfh[np][hf]);
                    mma16816(acc[mt][nt], afh, &bfl[np][hf]);
                    mma16816(acc[mt][nt], afl, &bfh[np][hf]);
                }
            }
        }
        __syncthreads();
    }

#pragma unroll
    for (int mt = 0; mt < 4; mt++) {
#pragma unroll
        for (int half = 0; half < 2; half++) {
            const int m = m0 + wm * 64 + mt * 16 + g + half * 8;
#pragma unroll
            for (int nt = 0; nt < 4; nt++) {
                const int n = n0 + wn * 32 + nt * 8 + tig * 2;
                const float v0 = acc[mt][nt][half * 2], v1 = acc[mt][nt][half * 2 + 1];
                if (REMAP) {
                    const int b = m >> 11, t = m & 2047;
                    const int h2 = n >> 6, d = n & 63;
                    const size_t off = (((size_t)(b * HH + h2)) * TT + t) * DD + d;
                    uint32_t ph, pl;
                    splitpack(v0, v1, ph, pl);
                    *(uint32_t*)(outH + off) = ph;
                    *(uint32_t*)(outL + off) = pl;
                } else {
                    *(float2*)(outF + (size_t)m * CC + n) = make_float2(v0, v1);
                }
            }
        }
    }
}

// ---------------------------------------------------------------------------
// Flash attention on HMMA (3-pass split bf16 for S and PV, causal).
// CTA: 256 thr (8 warps), Q-tile 128 rows (warp w owns rows q0+16w..+15),
// K-tile 64. V consumed via ldmatrix.trans. Output -> bf16 hi/lo [B,T,C].
// ---------------------------------------------------------------------------
#define KSB 144                      // smem row stride bytes (72 bf16)
#define OQH 0
#define OQL (OQH + 128 * KSB)        // 18432
#define OKH (OQL + 128 * KSB)        // 36864
#define OKL (OKH + 64 * KSB)         // 46080
#define OVH (OKL + 64 * KSB)         // 55296
#define OVL (OVH + 64 * KSB)         // 64512
#define FLASH_SMEM (OVL + 64 * KSB)  // 73728

__global__ __launch_bounds__(256, 2) void flash_hmma() {
    extern __shared__ __align__(128) char smem[];
    const uint32_t sb = smem_u32(smem);

    const int tid = threadIdx.x;
    const int w = tid >> 5;
    const int lane = tid & 31;
    const int g = lane >> 2, tig = lane & 3;
    const int q0 = ((int)gridDim.x - 1 - (int)blockIdx.x) * 128;
    const int bh = blockIdx.y;
    const int b = bh / HH, h = bh % HH;
    const int row0 = q0 + w * 16;

    const __nv_bfloat16* Qh_g = g_qh + (size_t)bh * TT * DD;
    const __nv_bfloat16* Ql_g = g_ql + (size_t)bh * TT * DD;
    const __nv_bfloat16* Kh_g = g_kh + (size_t)bh * TT * DD;
    const __nv_bfloat16* Kl_g = g_kl + (size_t)bh * TT * DD;
    const __nv_bfloat16* Vh_g = g_vh + (size_t)bh * TT * DD;
    const __nv_bfloat16* Vl_g = g_vl + (size_t)bh * TT * DD;

    // ---- load Q tile (hi+lo): 2048 cp16 ----
#pragma unroll
    for (int it = 0; it < 8; it++) {
        const int idx = it * 256 + tid;
        const int mat = idx >> 10;            // 0: hi, 1: lo
        const int r = (idx >> 3) & 127, c = idx & 7;
        const __nv_bfloat16* src = (mat ? Ql_g : Qh_g) + (size_t)(q0 + r) * DD + c * 8;
        cp16(sb + (mat ? OQL : OQH) + r * KSB + c * 16, src);
    }
    cp_commit();

    float o[8][4] = {};
    float mrow[2] = {-1e30f, -1e30f}, lrow[2] = {0.f, 0.f};
    const int nkt = (q0 >> 6) + 2;

    for (int kt = 0; kt < nkt; kt++) {
        const int k0 = kt << 6;
        __syncthreads();   // previous compute done with K/V
#pragma unroll
        for (int it = 0; it < 8; it++) {
            const int idx = it * 256 + tid;
            const int mat = idx >> 9;         // 0:Kh 1:Kl 2:Vh 3:Vl
            const int r = (idx >> 3) & 63, c = idx & 7;
            const __nv_bfloat16* src =
                (mat == 0 ? Kh_g : mat == 1 ? Kl_g : mat == 2 ? Vh_g : Vl_g)
                + (size_t)(k0 + r) * DD + c * 8;
            const uint32_t dst =
                (mat == 0 ? OKH : mat == 1 ? OKL : mat == 2 ? OVH : OVL);
            cp16(sb + dst + r * KSB + c * 16, src);
        }
        cp_commit();
        cp_wait<0>();
        __syncthreads();

        if (k0 <= row0 + 15) {   // warp has live rows in this k-tile
            // ---- S = Q K^T (3-pass) ----
            float s[8][4] = {};
#pragma unroll
            for (int ks = 0; ks < 4; ks++) {
                uint32_t qh[4], ql[4];
                const uint32_t ao = (w * 16 + (lane & 15)) * KSB + (lane >> 4) * 16 + ks * 32;
                ldsm4(qh, sb + OQH + ao);
                ldsm4(ql, sb + OQL + ao);
#pragma unroll
                for (int n16 = 0; n16 < 4; n16++) {
                    uint32_t kh[4], kl[4];
                    const uint32_t bo = (n16 * 16 + (lane & 7) + ((lane >> 4) & 1) * 8) * KSB
                                        + ((lane >> 3) & 1) * 16 + ks * 32;
                    ldsm4(kh, sb + OKH + bo);
                    ldsm4(kl, sb + OKL + bo);
#pragma unroll
                    for (int h2 = 0; h2 < 2; h2++) {
                        const int nt = n16 * 2 + h2;
                        mma16816(s[nt], qh, &kh[h2 * 2]);
                        mma16816(s[nt], qh, &kl[h2 * 2]);
                        mma16816(s[nt], ql, &kh[h2 * 2]);
                    }
                }
            }

            // ---- causal mask (only near diagonal) ----
            if (k0 + 63 > row0) {
#pragma unroll
                for (int nt = 0; nt < 8; nt++)
#pragma unroll
                    for (int e = 0; e < 4; e++) {
                        const int col = k0 + nt * 8 + tig * 2 + (e & 1);
                        const int row = row0 + g + (e >> 1) * 8;
                        if (col > row) s[nt][e] = -1e30f;
                    }
            }

            // ---- online softmax on fragments (rows g, g+8) ----
            const unsigned FULL = 0xffffffffu;
#pragma unroll
            for (int p2 = 0; p2 < 2; p2++) {
                float mx = -1e30f;
#pragma unroll
                for (int nt = 0; nt < 8; nt++)
                    mx = fmaxf(mx, fmaxf(s[nt][p2 * 2], s[nt][p2 * 2 + 1]));
                mx *= 0.125f;
                mx = fmaxf(mx, __shfl_xor_sync(FULL, mx, 1));
                mx = fmaxf(mx, __shfl_xor_sync(FULL, mx, 2));
                const float m_new = fmaxf(mrow[p2], mx);
                const float corr = __expf(mrow[p2] - m_new);
                float sum = 0.f;
#pragma unroll
                for (int nt = 0; nt < 8; nt++) {
                    const float e0 = __expf(s[nt][p2 * 2]     * 0.125f - m_new);
                    const float e1 = __expf(s[nt][p2 * 2 + 1] * 0.125f - m_new);
                    s[nt][p2 * 2] = e0; s[nt][p2 * 2 + 1] = e1;
                    sum += e0 + e1;
                }
                sum += __shfl_xor_sync(FULL, sum, 1);
                sum += __shfl_xor_sync(FULL, sum, 2);
                lrow[p2] = lrow[p2] * corr + sum;
                mrow[p2] = m_new;
#pragma unroll
                for (int nt = 0; nt < 8; nt++) {
                    o[nt][p2 * 2] *= corr; o[nt][p2 * 2 + 1] *= corr;
                }
            }

            // ---- O += P V (3-pass), P split per k-step ----
#pragma unroll
            for (int ks = 0; ks < 4; ks++) {
                uint32_t aH[4], aL[4];
                splitpack(s[2 * ks][0],     s[2 * ks][1],     aH[0], aL[0]);
                splitpack(s[2 * ks][2],     s[2 * ks][3],     aH[1], aL[1]);
                splitpack(s[2 * ks + 1][0], s[2 * ks + 1][1], aH[2], aL[2]);
                splitpack(s[2 * ks + 1][2], s[2 * ks + 1][3], aH[3], aL[3]);
#pragma unroll
                for (int n16 = 0; n16 < 4; n16++) {
                    uint32_t vh[4], vl[4];
                    const uint32_t vo = (ks * 16 + (lane & 15)) * KSB
                                        + n16 * 32 + ((lane >> 4) & 1) * 16;
                    ldsm4t(vh, sb + OVH + vo);
                    ldsm4t(vl, sb + OVL + vo);
#pragma unroll
                    for (int h2 = 0; h2 < 2; h2++) {
                        const int nt = n16 * 2 + h2;
                        mma16816(o[nt], aH, &vh[h2 * 2]);
                        mma16816(o[nt], aH, &vl[h2 * 2]);
                        mma16816(o[nt], aL, &vh[h2 * 2]);
                    }
                }
            }
        }
    }

    // ---- normalize + bf16 hi/lo split into Wo GEMM inputs ([B,T,C]) ----
#pragma unroll
    for (int p2 = 0; p2 < 2; p2++) {
        const float inv = 1.0f / lrow[p2];
        const int r = row0 + g + p2 * 8;
        const size_t base = ((size_t)(b * TT + r)) * CC + h * DD;
#pragma unroll
        for (int nt = 0; nt < 8; nt++) {
            uint32_t ph, pl;
            splitpack(o[nt][p2 * 2] * inv, o[nt][p2 * 2 + 1] * inv, ph, pl);
            *(uint32_t*)(g_ah + base + nt * 8 + tig * 2) = ph;
            *(uint32_t*)(g_al + base + nt * 8 + tig * 2) = pl;
        }
    }
}

// ---------------------------------------------------------------------------
extern "C" void kernel_launch(void* const* d_in, const int* in_sizes, int n_in,
                              void* d_out, int out_size) {
    const float* x  = (const float*)d_in[0];
    const float* Wq = (const float*)d_in[1];
    const float* Wk = (const float*)d_in[2];
    const float* Wv = (const float*)d_in[3];
    const float* Wo = (const float*)d_in[4];
    float* out = (float*)d_out;

    __nv_bfloat16 *qh, *ql, *kh, *kl, *vh, *vl, *xh, *xl, *ah, *al, *wh, *wl;
    cudaGetSymbolAddress((void**)&qh, g_qh); cudaGetSymbolAddress((void**)&ql, g_ql);
    cudaGetSymbolAddress((void**)&kh, g_kh); cudaGetSymbolAddress((void**)&kl, g_kl);
    cudaGetSymbolAddress((void**)&vh, g_vh); cudaGetSymbolAddress((void**)&vl, g_vl);
    cudaGetSymbolAddress((void**)&xh, g_xh); cudaGetSymbolAddress((void**)&xl, g_xl);
    cudaGetSymbolAddress((void**)&ah, g_ah); cudaGetSymbolAddress((void**)&al, g_al);
    cudaGetSymbolAddress((void**)&wh, g_wh); cudaGetSymbolAddress((void**)&wl, g_wl);

    split_bf16<<<(MM * CC / 4 + 255) / 256, 256>>>(x, xh, xl, MM * CC / 4);
    split_w4<<<dim3((CC * CC / 4 + 255) / 256, 4), 256>>>(Wq, Wk, Wv, Wo, wh, wl);

    const int gemm_smem = 2 * STAGEB;  // 81920
    cudaFuncSetAttribute(mma_gemm<1>, cudaFuncAttributeMaxDynamicSharedMemorySize, gemm_smem);
    cudaFuncSetAttribute(mma_gemm<0>, cudaFuncAttributeMaxDynamicSharedMemorySize, gemm_smem);
    cudaFuncSetAttribute(flash_hmma, cudaFuncAttributeMaxDynamicSharedMemorySize, FLASH_SMEM);

    dim3 gg(CC / 128, MM / 128);  // (8, 64)
    mma_gemm<1><<<gg, 256, gemm_smem>>>(xh, xl, wh + 0 * (size_t)CC * CC, wl + 0 * (size_t)CC * CC,
                                        nullptr, qh, ql);
    mma_gemm<1><<<gg, 256, gemm_smem>>>(xh, xl, wh + 1 * (size_t)CC * CC, wl + 1 * (size_t)CC * CC,
                                        nullptr, kh, kl);
    mma_gemm<1><<<gg, 256, gemm_smem>>>(xh, xl, wh + 2 * (size_t)CC * CC, wl + 2 * (size_t)CC * CC,
                                        nullptr, vh, vl);

    flash_hmma<<<dim3(TT / 128, BB * HH), 256, FLASH_SMEM>>>();

    mma_gemm<0><<<gg, 256, gemm_smem>>>(ah, al, wh + 3 * (size_t)CC * CC, wl + 3 * (size_t)CC * CC,
                                        out, nullptr, nullptr);
}

// round 12
// speedup vs baseline: 3.4797x; 1.0711x over previous
#include <cuda_runtime.h>
#include <cuda_bf16.h>
#include <math.h>
#include <stdint.h>

#define BB 4
#define TT 2048
#define CC 1024
#define HH 16
#define DD 64
#define MM (BB*TT)

// ---------------- scratch (device globals; no runtime alloc) ----------------
__device__ __nv_bfloat16 g_qh[(size_t)BB*HH*TT*DD], g_ql[(size_t)BB*HH*TT*DD];
__device__ __nv_bfloat16 g_kh[(size_t)BB*HH*TT*DD], g_kl[(size_t)BB*HH*TT*DD];
__device__ __nv_bfloat16 g_vh[(size_t)BB*HH*TT*DD], g_vl[(size_t)BB*HH*TT*DD];
__device__ __nv_bfloat16 g_xh[(size_t)MM*CC], g_xl[(size_t)MM*CC];
__device__ __nv_bfloat16 g_ah[(size_t)MM*CC], g_al[(size_t)MM*CC];
__device__ __nv_bfloat16 g_wh[4][(size_t)CC*CC], g_wl[4][(size_t)CC*CC];

// ---------------- base-ISA tensor helpers (compute_103-safe) ----------------
__device__ __forceinline__ uint32_t smem_u32(const void* p) {
    uint32_t a;
    asm("{ .reg .u64 t; cvta.to.shared.u64 t, %1; cvt.u32.u64 %0, t; }"
        : "=r"(a) : "l"(p));
    return a;
}
__device__ __forceinline__ void cp16(uint32_t dst, const void* src) {
    asm volatile("cp.async.cg.shared.global [%0], [%1], 16;" :: "r"(dst), "l"(src));
}
__device__ __forceinline__ void cp_commit() { asm volatile("cp.async.commit_group;"); }
template<int N> __device__ __forceinline__ void cp_wait() {
    asm volatile("cp.async.wait_group %0;" :: "n"(N));
}
__device__ __forceinline__ void ldsm4(uint32_t* r, uint32_t addr) {
    asm volatile("ldmatrix.sync.aligned.m8n8.x4.shared.b16 {%0,%1,%2,%3}, [%4];"
                 : "=r"(r[0]), "=r"(r[1]), "=r"(r[2]), "=r"(r[3]) : "r"(addr));
}
__device__ __forceinline__ void ldsm4t(uint32_t* r, uint32_t addr) {
    asm volatile("ldmatrix.sync.aligned.m8n8.x4.trans.shared.b16 {%0,%1,%2,%3}, [%4];"
                 : "=r"(r[0]), "=r"(r[1]), "=r"(r[2]), "=r"(r[3]) : "r"(addr));
}
__device__ __forceinline__ void mma16816(float* d, const uint32_t* a, const uint32_t* b) {
    asm volatile(
        "mma.sync.aligned.m16n8k16.row.col.f32.bf16.bf16.f32 "
        "{%0,%1,%2,%3}, {%4,%5,%6,%7}, {%8,%9}, {%0,%1,%2,%3};"
        : "+f"(d[0]), "+f"(d[1]), "+f"(d[2]), "+f"(d[3])
        : "r"(a[0]), "r"(a[1]), "r"(a[2]), "r"(a[3]), "r"(b[0]), "r"(b[1]));
}
__device__ __forceinline__ void splitpack(float a, float b, uint32_t& h, uint32_t& l) {
    __nv_bfloat162 hh = __floats2bfloat162_rn(a, b);
    float2 hf = __bfloat1622float2(hh);
    __nv_bfloat162 ll = __floats2bfloat162_rn(a - hf.x, b - hf.y);
    h = *reinterpret_cast<uint32_t*>(&hh);
    l = *reinterpret_cast<uint32_t*>(&ll);
}

// ---------------------------------------------------------------------------
// fp32 -> (bf16 hi, bf16 lo) split kernels
// ---------------------------------------------------------------------------
__device__ __forceinline__ void split_body(const float* __restrict__ src,
                                           __nv_bfloat16* __restrict__ hi,
                                           __nv_bfloat16* __restrict__ lo, int i) {
    float4 v = ((const float4*)src)[i];
    uint32_t h0, l0, h1, l1;
    splitpack(v.x, v.y, h0, l0);
    splitpack(v.z, v.w, h1, l1);
    ((uint32_t*)hi)[2 * i] = h0; ((uint32_t*)hi)[2 * i + 1] = h1;
    ((uint32_t*)lo)[2 * i] = l0; ((uint32_t*)lo)[2 * i + 1] = l1;
}
__global__ __launch_bounds__(256) void split_bf16(const float* __restrict__ src,
                                                  __nv_bfloat16* __restrict__ hi,
                                                  __nv_bfloat16* __restrict__ lo, int n4) {
    int i = blockIdx.x * 256 + threadIdx.x;
    if (i < n4) split_body(src, hi, lo, i);
}
__global__ __launch_bounds__(256) void split_w4(const float* __restrict__ w0,
                                                const float* __restrict__ w1,
                                                const float* __restrict__ w2,
                                                const float* __restrict__ w3,
                                                __nv_bfloat16* __restrict__ hi,
                                                __nv_bfloat16* __restrict__ lo) {
    const int which = blockIdx.y;
    const float* src = which == 0 ? w0 : which == 1 ? w1 : which == 2 ? w2 : w3;
    hi += (size_t)which * CC * CC;
    lo += (size_t)which * CC * CC;
    int i = blockIdx.x * 256 + threadIdx.x;
    if (i < CC * CC / 4) split_body(src, hi, lo, i);
}

// ---------------------------------------------------------------------------
// GEMM core (shared by fused-QKV and Wo kernels)
// ---------------------------------------------------------------------------
#define ROWB 80
#define MATB (128 * ROWB)
#define STAGEB (4 * MATB)
#define NCHUNK (CC / 32)

template<int REMAP>
__device__ __forceinline__ void gemm_core(
    const __nv_bfloat16* __restrict__ Ah_g, const __nv_bfloat16* __restrict__ Al_g,
    const __nv_bfloat16* __restrict__ Bh_g, const __nv_bfloat16* __restrict__ Bl_g,
    float* __restrict__ outF, __nv_bfloat16* __restrict__ outH,
    __nv_bfloat16* __restrict__ outL, char* smem, int m0, int n0) {

    const int tid = threadIdx.x;
    const int wid = tid >> 5;
    const int lane = tid & 31;
    const uint32_t sbase = smem_u32(smem);

    const char* srcs[4] = {
        (const char*)(Ah_g + (size_t)m0 * CC), (const char*)(Al_g + (size_t)m0 * CC),
        (const char*)(Bh_g + (size_t)n0 * CC), (const char*)(Bl_g + (size_t)n0 * CC)};

    auto stage_load = [&](int kc, int st) {
        const uint32_t dst0 = sbase + st * STAGEB;
        const size_t koff = (size_t)kc * 64;
#pragma unroll
        for (int mtx = 0; mtx < 4; mtx++) {
#pragma unroll
            for (int h2 = 0; h2 < 2; h2++) {
                const int idx = h2 * 256 + tid;
                const int r = idx >> 2, c = idx & 3;
                cp16(dst0 + mtx * MATB + r * ROWB + c * 16,
                     srcs[mtx] + (size_t)r * 2048 + koff + c * 16);
            }
        }
    };

    const int wm = wid >> 2, wn = wid & 3;
    const int g = lane >> 2, tig = lane & 3;
    float acc[4][4][4] = {};

    const int a_row = wm * 64 + (lane & 15);
    const int a_col = (lane >> 4) * 16;
    const int b_row = wn * 32 + (lane & 7) + ((lane >> 4) & 1) * 8;
    const int b_col = ((lane >> 3) & 1) * 16;

    stage_load(0, 0);
    cp_commit();

    for (int c = 0; c < NCHUNK; c++) {
        const int st = c & 1;
        if (c + 1 < NCHUNK) { stage_load(c + 1, (c + 1) & 1); cp_commit(); cp_wait<1>(); }
        else                { cp_wait<0>(); }
        __syncthreads();

        const uint32_t sAh = sbase + st * STAGEB;
        const uint32_t sAl = sAh + MATB;
        const uint32_t sBh = sAh + 2 * MATB;
        const uint32_t sBl = sAh + 3 * MATB;

#pragma unroll
        for (int s = 0; s < 2; s++) {
            const int k16 = s * 32;
            uint32_t bfh[2][4], bfl[2][4];
#pragma unroll
            for (int np = 0; np < 2; np++) {
                const uint32_t bo = (b_row + np * 16) * ROWB + b_col + k16;
                ldsm4(bfh[np], sBh + bo);
                ldsm4(bfl[np], sBl + bo);
            }
#pragma unroll
            for (int mt = 0; mt < 4; mt++) {
                uint32_t afh[4], afl[4];
                const uint32_t ao = (a_row + mt * 16) * ROWB + a_col + k16;
                ldsm4(afh, sAh + ao);
                ldsm4(afl, sAl + ao);
#pragma unroll
                for (int nt = 0; nt < 4; nt++) {
                    const int np = nt >> 1, hf = (nt & 1) * 2;
                    mma16816(acc[mt][nt], afh, &bfh[np][hf]);
                    mma16816(acc[mt][nt], afh, &bfl[np][hf]);
                    mma16816(acc[mt][nt], afl, &bfh[np][hf]);
                }
            }
        }
        __syncthreads();
    }

#pragma unroll
    for (int mt = 0; mt < 4; mt++) {
#pragma unroll
        for (int half = 0; half < 2; half++) {
            const int m = m0 + wm * 64 + mt * 16 + g + half * 8;
#pragma unroll
            for (int nt = 0; nt < 4; nt++) {
                const int n = n0 + wn * 32 + nt * 8 + tig * 2;
                const float v0 = acc[mt][nt][half * 2], v1 = acc[mt][nt][half * 2 + 1];
                if (REMAP) {
                    const int b = m >> 11, t = m & 2047;
                    const int h2 = (n & 1023) >> 6, d = n & 63;
                    const size_t off = (((size_t)(b * HH + h2)) * TT + t) * DD + d;
                    uint32_t ph, pl;
                    splitpack(v0, v1, ph, pl);
                    *(uint32_t*)(outH + off) = ph;
                    *(uint32_t*)(outL + off) = pl;
                } else {
                    *(float2*)(outF + (size_t)m * CC + n) = make_float2(v0, v1);
                }
            }
        }
    }
}

// Fused QKV: grid (24, 64). bid.x: [0,8)=Q, [8,16)=K, [16,24)=V.
__global__ __launch_bounds__(256) void qkv_gemm() {
    extern __shared__ __align__(128) char smem[];
    const int which = blockIdx.x >> 3;
    const int n0 = (blockIdx.x & 7) * 128;
    const int m0 = blockIdx.y * 128;
    __nv_bfloat16* outH = which == 0 ? g_qh : which == 1 ? g_kh : g_vh;
    __nv_bfloat16* outL = which == 0 ? g_ql : which == 1 ? g_kl : g_vl;
    gemm_core<1>(g_xh, g_xl, g_wh[which], g_wl[which], nullptr, outH, outL,
                 smem, m0, n0);
}

// Wo GEMM: fp32 output row-major.
__global__ __launch_bounds__(256) void wo_gemm(float* __restrict__ out) {
    extern __shared__ __align__(128) char smem[];
    gemm_core<0>(g_ah, g_al, g_wh[3], g_wl[3], out, nullptr, nullptr,
                 smem, blockIdx.y * 128, blockIdx.x * 128);
}

// ---------------------------------------------------------------------------
// Flash attention on HMMA (3-pass split bf16, causal), double-buffered K/V.
// CTA: 256 thr (8 warps), Q-tile 128 rows, K-tile 64.
// ---------------------------------------------------------------------------
#define KSB 144
#define OQH 0
#define OQL (OQH + 128 * KSB)            // 18432
#define OKV (OQL + 128 * KSB)            // 36864
#define KVSTG (4 * 64 * KSB)             // 36864 per stage
#define FLASH_SMEM (OKV + 2 * KVSTG)     // 110592

__global__ __launch_bounds__(256, 2) void flash_hmma() {
    extern __shared__ __align__(128) char smem[];
    const uint32_t sb = smem_u32(smem);

    const int tid = threadIdx.x;
    const int w = tid >> 5;
    const int lane = tid & 31;
    const int g = lane >> 2, tig = lane & 3;
    const int q0 = ((int)gridDim.x - 1 - (int)blockIdx.x) * 128;
    const int bh = blockIdx.y;
    const int b = bh / HH, h = bh % HH;
    const int row0 = q0 + w * 16;

    const __nv_bfloat16* Qh_g = g_qh + (size_t)bh * TT * DD;
    const __nv_bfloat16* Ql_g = g_ql + (size_t)bh * TT * DD;
    const __nv_bfloat16* Kh_g = g_kh + (size_t)bh * TT * DD;
    const __nv_bfloat16* Kl_g = g_kl + (size_t)bh * TT * DD;
    const __nv_bfloat16* Vh_g = g_vh + (size_t)bh * TT * DD;
    const __nv_bfloat16* Vl_g = g_vl + (size_t)bh * TT * DD;

    // ---- Q tile (hi+lo) ----
#pragma unroll
    for (int it = 0; it < 8; it++) {
        const int idx = it * 256 + tid;
        const int mat = idx >> 10;
        const int r = (idx >> 3) & 127, c = idx & 7;
        const __nv_bfloat16* src = (mat ? Ql_g : Qh_g) + (size_t)(q0 + r) * DD + c * 8;
        cp16(sb + (mat ? OQL : OQH) + r * KSB + c * 16, src);
    }
    cp_commit();

    auto kv_load = [&](int kt, int st) {
        const int k0 = kt << 6;
        const uint32_t base = sb + OKV + st * KVSTG;
#pragma unroll
        for (int it = 0; it < 8; it++) {
            const int idx = it * 256 + tid;
            const int mat = idx >> 9;     // 0:Kh 1:Kl 2:Vh 3:Vl
            const int r = (idx >> 3) & 63, c = idx & 7;
            const __nv_bfloat16* src =
                (mat == 0 ? Kh_g : mat == 1 ? Kl_g : mat == 2 ? Vh_g : Vl_g)
                + (size_t)(k0 + r) * DD + c * 8;
            cp16(base + mat * (64 * KSB) + r * KSB + c * 16, src);
        }
        cp_commit();
    };

    float o[8][4] = {};
    float mrow[2] = {-1e30f, -1e30f}, lrow[2] = {0.f, 0.f};
    const int nkt = (q0 >> 6) + 2;

    kv_load(0, 0);

    for (int kt = 0; kt < nkt; kt++) {
        const int k0 = kt << 6;
        const int st = kt & 1;
        if (kt + 1 < nkt) { kv_load(kt + 1, st ^ 1); cp_wait<1>(); }
        else              { cp_wait<0>(); }
        __syncthreads();

        const uint32_t kvb = sb + OKV + st * KVSTG;
        const uint32_t sKH = kvb, sKL = kvb + 64 * KSB;
        const uint32_t sVH = kvb + 2 * 64 * KSB, sVL = kvb + 3 * 64 * KSB;

        if (k0 <= row0 + 15) {
            // ---- S = Q K^T (3-pass) ----
            float s[8][4] = {};
#pragma unroll
            for (int ks = 0; ks < 4; ks++) {
                uint32_t qh[4], ql[4];
                const uint32_t ao = (w * 16 + (lane & 15)) * KSB + (lane >> 4) * 16 + ks * 32;
                ldsm4(qh, sb + OQH + ao);
                ldsm4(ql, sb + OQL + ao);
#pragma unroll
                for (int n16 = 0; n16 < 4; n16++) {
                    uint32_t kh[4], kl[4];
                    const uint32_t bo = (n16 * 16 + (lane & 7) + ((lane >> 4) & 1) * 8) * KSB
                                        + ((lane >> 3) & 1) * 16 + ks * 32;
                    ldsm4(kh, sKH + bo);
                    ldsm4(kl, sKL + bo);
#pragma unroll
                    for (int h2 = 0; h2 < 2; h2++) {
                        const int nt = n16 * 2 + h2;
                        mma16816(s[nt], qh, &kh[h2 * 2]);
                        mma16816(s[nt], qh, &kl[h2 * 2]);
                        mma16816(s[nt], ql, &kh[h2 * 2]);
                    }
                }
            }

            // ---- causal mask ----
            if (k0 + 63 > row0) {
#pragma unroll
                for (int nt = 0; nt < 8; nt++)
#pragma unroll
                    for (int e = 0; e < 4; e++) {
                        const int col = k0 + nt * 8 + tig * 2 + (e & 1);
                        const int row = row0 + g + (e >> 1) * 8;
                        if (col > row) s[nt][e] = -1e30f;
                    }
            }

            // ---- online softmax on fragments ----
            const unsigned FULL = 0xffffffffu;
#pragma unroll
            for (int p2 = 0; p2 < 2; p2++) {
                float mx = -1e30f;
#pragma unroll
                for (int nt = 0; nt < 8; nt++)
                    mx = fmaxf(mx, fmaxf(s[nt][p2 * 2], s[nt][p2 * 2 + 1]));
                mx *= 0.125f;
                mx = fmaxf(mx, __shfl_xor_sync(FULL, mx, 1));
                mx = fmaxf(mx, __shfl_xor_sync(FULL, mx, 2));
                const float m_new = fmaxf(mrow[p2], mx);
                const float corr = __expf(mrow[p2] - m_new);
                float sum = 0.f;
#pragma unroll
                for (int nt = 0; nt < 8; nt++) {
                    const float e0 = __expf(s[nt][p2 * 2]     * 0.125f - m_new);
                    const float e1 = __expf(s[nt][p2 * 2 + 1] * 0.125f - m_new);
                    s[nt][p2 * 2] = e0; s[nt][p2 * 2 + 1] = e1;
                    sum += e0 + e1;
                }
                sum += __shfl_xor_sync(FULL, sum, 1);
                sum += __shfl_xor_sync(FULL, sum, 2);
                lrow[p2] = lrow[p2] * corr + sum;
                mrow[p2] = m_new;
#pragma unroll
                for (int nt = 0; nt < 8; nt++) {
                    o[nt][p2 * 2] *= corr; o[nt][p2 * 2 + 1] *= corr;
                }
            }

            // ---- O += P V (3-pass) ----
#pragma unroll
            for (int ks = 0; ks < 4; ks++) {
                uint32_t aH[4], aL[4];
                splitpack(s[2 * ks][0],     s[2 * ks][1],     aH[0], aL[0]);
                splitpack(s[2 * ks][2],     s[2 * ks][3],     aH[1], aL[1]);
                splitpack(s[2 * ks + 1][0], s[2 * ks + 1][1], aH[2], aL[2]);
                splitpack(s[2 * ks + 1][2], s[2 * ks + 1][3], aH[3], aL[3]);
#pragma unroll
                for (int n16 = 0; n16 < 4; n16++) {
                    uint32_t vh[4], vl[4];
                    const uint32_t vo = (ks * 16 + (lane & 15)) * KSB
                                        + n16 * 32 + ((lane >> 4) & 1) * 16;
                    ldsm4t(vh, sVH + vo);
                    ldsm4t(vl, sVL + vo);
#pragma unroll
                    for (int h2 = 0; h2 < 2; h2++) {
                        const int nt = n16 * 2 + h2;
                        mma16816(o[nt], aH, &vh[h2 * 2]);
                        mma16816(o[nt], aH, &vl[h2 * 2]);
                        mma16816(o[nt], aL, &vh[h2 * 2]);
                    }
                }
            }
        }
        __syncthreads();   // all warps done with stage st before it is refilled
    }

    // ---- normalize + bf16 hi/lo split into Wo GEMM inputs ----
#pragma unroll
    for (int p2 = 0; p2 < 2; p2++) {
        const float inv = 1.0f / lrow[p2];
        const int r = row0 + g + p2 * 8;
        const size_t base = ((size_t)(b * TT + r)) * CC + h * DD;
#pragma unroll
        for (int nt = 0; nt < 8; nt++) {
            uint32_t ph, pl;
            splitpack(o[nt][p2 * 2] * inv, o[nt][p2 * 2 + 1] * inv, ph, pl);
            *(uint32_t*)(g_ah + base + nt * 8 + tig * 2) = ph;
            *(uint32_t*)(g_al + base + nt * 8 + tig * 2) = pl;
        }
    }
}

// ---------------------------------------------------------------------------
extern "C" void kernel_launch(void* const* d_in, const int* in_sizes, int n_in,
                              void* d_out, int out_size) {
    const float* x  = (const float*)d_in[0];
    const float* Wq = (const float*)d_in[1];
    const float* Wk = (const float*)d_in[2];
    const float* Wv = (const float*)d_in[3];
    const float* Wo = (const float*)d_in[4];
    float* out = (float*)d_out;

    __nv_bfloat16 *xh, *xl, *wh, *wl;
    cudaGetSymbolAddress((void**)&xh, g_xh); cudaGetSymbolAddress((void**)&xl, g_xl);
    cudaGetSymbolAddress((void**)&wh, g_wh); cudaGetSymbolAddress((void**)&wl, g_wl);

    split_bf16<<<(MM * CC / 4 + 255) / 256, 256>>>(x, xh, xl, MM * CC / 4);
    split_w4<<<dim3((CC * CC / 4 + 255) / 256, 4), 256>>>(Wq, Wk, Wv, Wo, wh, wl);

    const int gemm_smem = 2 * STAGEB;  // 81920
    cudaFuncSetAttribute(qkv_gemm, cudaFuncAttributeMaxDynamicSharedMemorySize, gemm_smem);
    cudaFuncSetAttribute(wo_gemm, cudaFuncAttributeMaxDynamicSharedMemorySize, gemm_smem);
    cudaFuncSetAttribute(flash_hmma, cudaFuncAttributeMaxDynamicSharedMemorySize, FLASH_SMEM);

    qkv_gemm<<<dim3(24, MM / 128), 256, gemm_smem>>>();

    flash_hmma<<<dim3(TT / 128, BB * HH), 256, FLASH_SMEM>>>();

    wo_gemm<<<dim3(CC / 128, MM / 128), 256, gemm_smem>>>(out);
}

// round 13
// speedup vs baseline: 4.5202x; 1.2990x over previous
#include <cuda_runtime.h>
#include <cuda_fp16.h>
#include <math.h>
#include <stdint.h>

#define BB 4
#define TT 2048
#define CC 1024
#define HH 16
#define DD 64
#define MM (BB*TT)

// ---------------- scratch (device globals; no runtime alloc) ----------------
__device__ __half g_qh[(size_t)BB*HH*TT*DD], g_ql[(size_t)BB*HH*TT*DD];
__device__ __half g_kh[(size_t)BB*HH*TT*DD], g_kl[(size_t)BB*HH*TT*DD];
__device__ __half g_vh[(size_t)BB*HH*TT*DD], g_vl[(size_t)BB*HH*TT*DD];
__device__ __half g_xh[(size_t)MM*CC], g_xl[(size_t)MM*CC];
__device__ __half g_ah[(size_t)MM*CC], g_al[(size_t)MM*CC];
__device__ __half g_wh[4][(size_t)CC*CC];

// ---------------- base-ISA tensor helpers (compute_103-safe) ----------------
__device__ __forceinline__ uint32_t smem_u32(const void* p) {
    uint32_t a;
    asm("{ .reg .u64 t; cvta.to.shared.u64 t, %1; cvt.u32.u64 %0, t; }"
        : "=r"(a) : "l"(p));
    return a;
}
__device__ __forceinline__ void cp16(uint32_t dst, const void* src) {
    asm volatile("cp.async.cg.shared.global [%0], [%1], 16;" :: "r"(dst), "l"(src));
}
__device__ __forceinline__ void cp_commit() { asm volatile("cp.async.commit_group;"); }
template<int N> __device__ __forceinline__ void cp_wait() {
    asm volatile("cp.async.wait_group %0;" :: "n"(N));
}
__device__ __forceinline__ void ldsm4(uint32_t* r, uint32_t addr) {
    asm volatile("ldmatrix.sync.aligned.m8n8.x4.shared.b16 {%0,%1,%2,%3}, [%4];"
                 : "=r"(r[0]), "=r"(r[1]), "=r"(r[2]), "=r"(r[3]) : "r"(addr));
}
__device__ __forceinline__ void ldsm4t(uint32_t* r, uint32_t addr) {
    asm volatile("ldmatrix.sync.aligned.m8n8.x4.trans.shared.b16 {%0,%1,%2,%3}, [%4];"
                 : "=r"(r[0]), "=r"(r[1]), "=r"(r[2]), "=r"(r[3]) : "r"(addr));
}
__device__ __forceinline__ void mma16816(float* d, const uint32_t* a, const uint32_t* b) {
    asm volatile(
        "mma.sync.aligned.m16n8k16.row.col.f32.f16.f16.f32 "
        "{%0,%1,%2,%3}, {%4,%5,%6,%7}, {%8,%9}, {%0,%1,%2,%3};"
        : "+f"(d[0]), "+f"(d[1]), "+f"(d[2]), "+f"(d[3])
        : "r"(a[0]), "r"(a[1]), "r"(a[2]), "r"(a[3]), "r"(b[0]), "r"(b[1]));
}
// split 2 fp32 -> packed half2 hi + packed half2 lo residual
__device__ __forceinline__ void splitpack(float a, float b, uint32_t& h, uint32_t& l) {
    __half2 hh = __floats2half2_rn(a, b);
    float2 hf = __half22float2(hh);
    __half2 ll = __floats2half2_rn(a - hf.x, b - hf.y);
    h = *reinterpret_cast<uint32_t*>(&hh);
    l = *reinterpret_cast<uint32_t*>(&ll);
}
__device__ __forceinline__ uint32_t pack_h2(float a, float b) {
    __half2 hh = __floats2half2_rn(a, b);
    return *reinterpret_cast<uint32_t*>(&hh);
}

// ---------------------------------------------------------------------------
// fp32 -> (fp16 hi, fp16 lo) split kernels
// ---------------------------------------------------------------------------
__global__ __launch_bounds__(256) void split_half(const float* __restrict__ src,
                                                  __half* __restrict__ hi,
                                                  __half* __restrict__ lo, int n4) {
    int i = blockIdx.x * 256 + threadIdx.x;
    if (i >= n4) return;
    float4 v = ((const float4*)src)[i];
    uint32_t h0, l0, h1, l1;
    splitpack(v.x, v.y, h0, l0);
    splitpack(v.z, v.w, h1, l1);
    ((uint32_t*)hi)[2 * i] = h0; ((uint32_t*)hi)[2 * i + 1] = h1;
    ((uint32_t*)lo)[2 * i] = l0; ((uint32_t*)lo)[2 * i + 1] = l1;
}
// weights: hi only (2-pass GEMM drops B-lo)
__global__ __launch_bounds__(256) void split_w4(const float* __restrict__ w0,
                                                const float* __restrict__ w1,
                                                const float* __restrict__ w2,
                                                const float* __restrict__ w3,
                                                __half* __restrict__ hi) {
    const int which = blockIdx.y;
    const float* src = which == 0 ? w0 : which == 1 ? w1 : which == 2 ? w2 : w3;
    hi += (size_t)which * CC * CC;
    int i = blockIdx.x * 256 + threadIdx.x;
    if (i >= CC * CC / 4) return;
    float4 v = ((const float4*)src)[i];
    ((uint32_t*)hi)[2 * i]     = pack_h2(v.x, v.y);
    ((uint32_t*)hi)[2 * i + 1] = pack_h2(v.z, v.w);
}

// ---------------------------------------------------------------------------
// GEMM core: out = A * B^T, 2-pass fp16 split: D = (Ah + Al) * Bh.
// Stage = 3 matrices (Ah | Al | Bh), K-chunk 32, double-buffered.
// ---------------------------------------------------------------------------
#define ROWB 80
#define MATB (128 * ROWB)
#define STAGEB (3 * MATB)          // 30720
#define NCHUNK (CC / 32)

template<int REMAP>
__device__ __forceinline__ void gemm_core(
    const __half* __restrict__ Ah_g, const __half* __restrict__ Al_g,
    const __half* __restrict__ Bh_g,
    float* __restrict__ outF, __half* __restrict__ outH,
    __half* __restrict__ outL, char* smem, int m0, int n0) {

    const int tid = threadIdx.x;
    const int wid = tid >> 5;
    const int lane = tid & 31;
    const uint32_t sbase = smem_u32(smem);

    const char* srcs[3] = {
        (const char*)(Ah_g + (size_t)m0 * CC), (const char*)(Al_g + (size_t)m0 * CC),
        (const char*)(Bh_g + (size_t)n0 * CC)};

    auto stage_load = [&](int kc, int st) {
        const uint32_t dst0 = sbase + st * STAGEB;
        const size_t koff = (size_t)kc * 64;
#pragma unroll
        for (int mtx = 0; mtx < 3; mtx++) {
#pragma unroll
            for (int h2 = 0; h2 < 2; h2++) {
                const int idx = h2 * 256 + tid;
                const int r = idx >> 2, c = idx & 3;
                cp16(dst0 + mtx * MATB + r * ROWB + c * 16,
                     srcs[mtx] + (size_t)r * 2048 + koff + c * 16);
            }
        }
    };

    const int wm = wid >> 2, wn = wid & 3;
    const int g = lane >> 2, tig = lane & 3;
    float acc[4][4][4] = {};

    const int a_row = wm * 64 + (lane & 15);
    const int a_col = (lane >> 4) * 16;
    const int b_row = wn * 32 + (lane & 7) + ((lane >> 4) & 1) * 8;
    const int b_col = ((lane >> 3) & 1) * 16;

    stage_load(0, 0);
    cp_commit();

    for (int c = 0; c < NCHUNK; c++) {
        const int st = c & 1;
        if (c + 1 < NCHUNK) { stage_load(c + 1, (c + 1) & 1); cp_commit(); cp_wait<1>(); }
        else                { cp_wait<0>(); }
        __syncthreads();

        const uint32_t sAh = sbase + st * STAGEB;
        const uint32_t sAl = sAh + MATB;
        const uint32_t sBh = sAh + 2 * MATB;

#pragma unroll
        for (int s = 0; s < 2; s++) {
            const int k16 = s * 32;
            uint32_t bfh[2][4];
#pragma unroll
            for (int np = 0; np < 2; np++)
                ldsm4(bfh[np], sBh + (b_row + np * 16) * ROWB + b_col + k16);
#pragma unroll
            for (int mt = 0; mt < 4; mt++) {
                uint32_t afh[4], afl[4];
                const uint32_t ao = (a_row + mt * 16) * ROWB + a_col + k16;
                ldsm4(afh, sAh + ao);
                ldsm4(afl, sAl + ao);
#pragma unroll
                for (int nt = 0; nt < 4; nt++) {
                    const int np = nt >> 1, hf = (nt & 1) * 2;
                    mma16816(acc[mt][nt], afh, &bfh[np][hf]);
                    mma16816(acc[mt][nt], afl, &bfh[np][hf]);
                }
            }
        }
        __syncthreads();
    }

#pragma unroll
    for (int mt = 0; mt < 4; mt++) {
#pragma unroll
        for (int half = 0; half < 2; half++) {
            const int m = m0 + wm * 64 + mt * 16 + g + half * 8;
#pragma unroll
            for (int nt = 0; nt < 4; nt++) {
                const int n = n0 + wn * 32 + nt * 8 + tig * 2;
                const float v0 = acc[mt][nt][half * 2], v1 = acc[mt][nt][half * 2 + 1];
                if (REMAP) {
                    const int b = m >> 11, t = m & 2047;
                    const int h2 = (n & 1023) >> 6, d = n & 63;
                    const size_t off = (((size_t)(b * HH + h2)) * TT + t) * DD + d;
                    uint32_t ph, pl;
                    splitpack(v0, v1, ph, pl);
                    *(uint32_t*)(outH + off) = ph;
                    *(uint32_t*)(outL + off) = pl;
                } else {
                    *(float2*)(outF + (size_t)m * CC + n) = make_float2(v0, v1);
                }
            }
        }
    }
}

// Fused QKV: grid (24, 64). bid.x: [0,8)=Q, [8,16)=K, [16,24)=V.
__global__ __launch_bounds__(256) void qkv_gemm() {
    extern __shared__ __align__(128) char smem[];
    const int which = blockIdx.x >> 3;
    const int n0 = (blockIdx.x & 7) * 128;
    const int m0 = blockIdx.y * 128;
    __half* outH = which == 0 ? g_qh : which == 1 ? g_kh : g_vh;
    __half* outL = which == 0 ? g_ql : which == 1 ? g_kl : g_vl;
    gemm_core<1>(g_xh, g_xl, g_wh[which], nullptr, outH, outL, smem, m0, n0);
}

__global__ __launch_bounds__(256) void wo_gemm(float* __restrict__ out) {
    extern __shared__ __align__(128) char smem[];
    gemm_core<0>(g_ah, g_al, g_wh[3], out, nullptr, nullptr,
                 smem, blockIdx.y * 128, blockIdx.x * 128);
}

// ---------------------------------------------------------------------------
// Flash attention: S = QK^T 3-pass fp16, PV 2-pass (Ph*Vh + Ph*Vl, no P split).
// CTA: 256 thr (8 warps), Q-tile 128 rows, K-tile 64, double-buffered K/V.
// ---------------------------------------------------------------------------
#define KSB 144
#define OQH 0
#define OQL (OQH + 128 * KSB)
#define OKV (OQL + 128 * KSB)            // 36864
#define KVSTG (4 * 64 * KSB)             // 36864
#define FLASH_SMEM (OKV + 2 * KVSTG)     // 110592

__global__ __launch_bounds__(256, 2) void flash_hmma() {
    extern __shared__ __align__(128) char smem[];
    const uint32_t sb = smem_u32(smem);

    const int tid = threadIdx.x;
    const int w = tid >> 5;
    const int lane = tid & 31;
    const int g = lane >> 2, tig = lane & 3;
    const int q0 = ((int)gridDim.x - 1 - (int)blockIdx.x) * 128;
    const int bh = blockIdx.y;
    const int b = bh / HH, h = bh % HH;
    const int row0 = q0 + w * 16;

    const __half* Qh_g = g_qh + (size_t)bh * TT * DD;
    const __half* Ql_g = g_ql + (size_t)bh * TT * DD;
    const __half* Kh_g = g_kh + (size_t)bh * TT * DD;
    const __half* Kl_g = g_kl + (size_t)bh * TT * DD;
    const __half* Vh_g = g_vh + (size_t)bh * TT * DD;
    const __half* Vl_g = g_vl + (size_t)bh * TT * DD;

#pragma unroll
    for (int it = 0; it < 8; it++) {
        const int idx = it * 256 + tid;
        const int mat = idx >> 10;
        const int r = (idx >> 3) & 127, c = idx & 7;
        const __half* src = (mat ? Ql_g : Qh_g) + (size_t)(q0 + r) * DD + c * 8;
        cp16(sb + (mat ? OQL : OQH) + r * KSB + c * 16, src);
    }
    cp_commit();

    auto kv_load = [&](int kt, int st) {
        const int k0 = kt << 6;
        const uint32_t base = sb + OKV + st * KVSTG;
#pragma unroll
        for (int it = 0; it < 8; it++) {
            const int idx = it * 256 + tid;
            const int mat = idx >> 9;     // 0:Kh 1:Kl 2:Vh 3:Vl
            const int r = (idx >> 3) & 63, c = idx & 7;
            const __half* src =
                (mat == 0 ? Kh_g : mat == 1 ? Kl_g : mat == 2 ? Vh_g : Vl_g)
                + (size_t)(k0 + r) * DD + c * 8;
            cp16(base + mat * (64 * KSB) + r * KSB + c * 16, src);
        }
        cp_commit();
    };

    float o[8][4] = {};
    float mrow[2] = {-1e30f, -1e30f}, lrow[2] = {0.f, 0.f};
    const int nkt = (q0 >> 6) + 2;

    kv_load(0, 0);

    for (int kt = 0; kt < nkt; kt++) {
        const int k0 = kt << 6;
        const int st = kt & 1;
        if (kt + 1 < nkt) { kv_load(kt + 1, st ^ 1); cp_wait<1>(); }
        else              { cp_wait<0>(); }
        __syncthreads();

        const uint32_t kvb = sb + OKV + st * KVSTG;
        const uint32_t sKH = kvb, sKL = kvb + 64 * KSB;
        const uint32_t sVH = kvb + 2 * 64 * KSB, sVL = kvb + 3 * 64 * KSB;

        if (k0 <= row0 + 15) {
            // ---- S = Q K^T (3-pass fp16) ----
            float s[8][4] = {};
#pragma unroll
            for (int ks = 0; ks < 4; ks++) {
                uint32_t qh[4], ql[4];
                const uint32_t ao = (w * 16 + (lane & 15)) * KSB + (lane >> 4) * 16 + ks * 32;
                ldsm4(qh, sb + OQH + ao);
                ldsm4(ql, sb + OQL + ao);
#pragma unroll
                for (int n16 = 0; n16 < 4; n16++) {
                    uint32_t kh[4], kl[4];
                    const uint32_t bo = (n16 * 16 + (lane & 7) + ((lane >> 4) & 1) * 8) * KSB
                                        + ((lane >> 3) & 1) * 16 + ks * 32;
                    ldsm4(kh, sKH + bo);
                    ldsm4(kl, sKL + bo);
#pragma unroll
                    for (int h2 = 0; h2 < 2; h2++) {
                        const int nt = n16 * 2 + h2;
                        mma16816(s[nt], qh, &kh[h2 * 2]);
                        mma16816(s[nt], qh, &kl[h2 * 2]);
                        mma16816(s[nt], ql, &kh[h2 * 2]);
                    }
                }
            }

            // ---- causal mask ----
            if (k0 + 63 > row0) {
#pragma unroll
                for (int nt = 0; nt < 8; nt++)
#pragma unroll
                    for (int e = 0; e < 4; e++) {
                        const int col = k0 + nt * 8 + tig * 2 + (e & 1);
                        const int row = row0 + g + (e >> 1) * 8;
                        if (col > row) s[nt][e] = -1e30f;
                    }
            }

            // ---- online softmax on fragments ----
            const unsigned FULL = 0xffffffffu;
#pragma unroll
            for (int p2 = 0; p2 < 2; p2++) {
                float mx = -1e30f;
#pragma unroll
                for (int nt = 0; nt < 8; nt++)
                    mx = fmaxf(mx, fmaxf(s[nt][p2 * 2], s[nt][p2 * 2 + 1]));
                mx *= 0.125f;
                mx = fmaxf(mx, __shfl_xor_sync(FULL, mx, 1));
                mx = fmaxf(mx, __shfl_xor_sync(FULL, mx, 2));
                const float m_new = fmaxf(mrow[p2], mx);
                const float corr = __expf(mrow[p2] - m_new);
                float sum = 0.f;
#pragma unroll
                for (int nt = 0; nt < 8; nt++) {
                    const float e0 = __expf(s[nt][p2 * 2]     * 0.125f - m_new);
                    const float e1 = __expf(s[nt][p2 * 2 + 1] * 0.125f - m_new);
                    s[nt][p2 * 2] = e0; s[nt][p2 * 2 + 1] = e1;
                    sum += e0 + e1;
                }
                sum += __shfl_xor_sync(FULL, sum, 1);
                sum += __shfl_xor_sync(FULL, sum, 2);
                lrow[p2] = lrow[p2] * corr + sum;
                mrow[p2] = m_new;
#pragma unroll
                for (int nt = 0; nt < 8; nt++) {
                    o[nt][p2 * 2] *= corr; o[nt][p2 * 2 + 1] *= corr;
                }
            }

            // ---- O += P V (2-pass: Ph*Vh + Ph*Vl) ----
#pragma unroll
            for (int ks = 0; ks < 4; ks++) {
                uint32_t aH[4];
                aH[0] = pack_h2(s[2 * ks][0],     s[2 * ks][1]);
                aH[1] = pack_h2(s[2 * ks][2],     s[2 * ks][3]);
                aH[2] = pack_h2(s[2 * ks + 1][0], s[2 * ks + 1][1]);
                aH[3] = pack_h2(s[2 * ks + 1][2], s[2 * ks + 1][3]);
#pragma unroll
                for (int n16 = 0; n16 < 4; n16++) {
                    uint32_t vh[4], vl[4];
                    const uint32_t vo = (ks * 16 + (lane & 15)) * KSB
                                        + n16 * 32 + ((lane >> 4) & 1) * 16;
                    ldsm4t(vh, sVH + vo);
                    ldsm4t(vl, sVL + vo);
#pragma unroll
                    for (int h2 = 0; h2 < 2; h2++) {
                        const int nt = n16 * 2 + h2;
                        mma16816(o[nt], aH, &vh[h2 * 2]);
                        mma16816(o[nt], aH, &vl[h2 * 2]);
                    }
                }
            }
        }
        __syncthreads();
    }

    // ---- normalize + fp16 hi/lo split into Wo GEMM inputs ----
#pragma unroll
    for (int p2 = 0; p2 < 2; p2++) {
        const float inv = 1.0f / lrow[p2];
        const int r = row0 + g + p2 * 8;
        const size_t base = ((size_t)(b * TT + r)) * CC + h * DD;
#pragma unroll
        for (int nt = 0; nt < 8; nt++) {
            uint32_t ph, pl;
            splitpack(o[nt][p2 * 2] * inv, o[nt][p2 * 2 + 1] * inv, ph, pl);
            *(uint32_t*)(g_ah + base + nt * 8 + tig * 2) = ph;
            *(uint32_t*)(g_al + base + nt * 8 + tig * 2) = pl;
        }
    }
}

// ---------------------------------------------------------------------------
extern "C" void kernel_launch(void* const* d_in, const int* in_sizes, int n_in,
                              void* d_out, int out_size) {
    const float* x  = (const float*)d_in[0];
    const float* Wq = (const float*)d_in[1];
    const float* Wk = (const float*)d_in[2];
    const float* Wv = (const float*)d_in[3];
    const float* Wo = (const float*)d_in[4];
    float* out = (float*)d_out;

    __half *xh, *xl, *wh;
    cudaGetSymbolAddress((void**)&xh, g_xh);
    cudaGetSymbolAddress((void**)&xl, g_xl);
    cudaGetSymbolAddress((void**)&wh, g_wh);

    split_half<<<(MM * CC / 4 + 255) / 256, 256>>>(x, xh, xl, MM * CC / 4);
    split_w4<<<dim3((CC * CC / 4 + 255) / 256, 4), 256>>>(Wq, Wk, Wv, Wo, wh);

    const int gemm_smem = 2 * STAGEB;  // 61440
    cudaFuncSetAttribute(qkv_gemm, cudaFuncAttributeMaxDynamicSharedMemorySize, gemm_smem);
    cudaFuncSetAttribute(wo_gemm, cudaFuncAttributeMaxDynamicSharedMemorySize, gemm_smem);
    cudaFuncSetAttribute(flash_hmma, cudaFuncAttributeMaxDynamicSharedMemorySize, FLASH_SMEM);

    qkv_gemm<<<dim3(24, MM / 128), 256, gemm_smem>>>();

    flash_hmma<<<dim3(TT / 128, BB * HH), 256, FLASH_SMEM>>>();

    wo_gemm<<<dim3(CC / 128, MM / 128), 256, gemm_smem>>>(out);
}